// round 6
// baseline (speedup 1.0000x reference)
#include <cuda_runtime.h>
#include <cstdint>

// Problem constants (match reference: N, E, F_IN, H, D)
#define NNODES 50000
#define NEDGES 800000
#define FDIM   128      // F_IN == H*D == 128
#define NHEADS 4
#define HDIM   32

// ---------------- device scratch (no allocations allowed) ----------------
__device__ __align__(16) float g_h[NNODES * FDIM];     // x @ W (25.6 MB)
__device__ float g_alpha_l[NNODES * NHEADS];
__device__ float g_alpha_r[NNODES * NHEADS];
__device__ int   g_cnt[NNODES];                        // histogram, then cursor
__device__ int   g_off[NNODES + 1];                    // CSR offsets by destination
__device__ int   g_src[NEDGES];                        // src per edge, sorted by dst
__device__ int   g_is64;                               // edge dtype: 1 = int64, 0 = int32

__device__ __forceinline__ int clamp_node(int v) {
    v = v < 0 ? 0 : v;
    return v >= NNODES ? NNODES - 1 : v;
}

// ---------------- K-1: probe edge dtype ----------------
// If data is little-endian int64 (values < 50000), every odd int32 word is 0.
// If data is int32, odd words are node ids (all-zero prob ~ (2e-5)^32 ~ 0).
__global__ void k_probe(const int* __restrict__ ei32) {
    int t = threadIdx.x;                 // 32 threads
    int v = ei32[2 * t + 1];
    unsigned nz = __ballot_sync(0xffffffffu, v != 0);
    if (t == 0) g_is64 = (nz == 0u) ? 1 : 0;
}

// ---------------- K0: zero histogram ----------------
__global__ void k_init_cnt() {
    int i = blockIdx.x * blockDim.x + threadIdx.x;
    if (i < NNODES) g_cnt[i] = 0;
}

// ---------------- K1: histogram of destinations ----------------
__global__ void k_hist(const int* __restrict__ ei32) {
    int i = blockIdx.x * blockDim.x + threadIdx.x;
    if (i < NEDGES) {
        int idx = NEDGES + i;
        int to = g_is64 ? ei32[2 * idx] : ei32[idx];
        atomicAdd(&g_cnt[clamp_node(to)], 1);
    }
}

// ---------------- K2: single-block exclusive scan (warp-shuffle) ----------------
__global__ __launch_bounds__(1024) void k_scan() {
    __shared__ int warp_sums[32];
    __shared__ int s_carry;
    __shared__ int s_incl_last;
    const int tid = threadIdx.x;
    const int lane = tid & 31, wid = tid >> 5;
    if (tid == 0) s_carry = 0;
    __syncthreads();

    for (int base = 0; base < NNODES; base += 1024) {
        int carry = s_carry;
        int i = base + tid;
        int v = (i < NNODES) ? g_cnt[i] : 0;
        int x = v;                       // inclusive warp scan
        #pragma unroll
        for (int o = 1; o < 32; o <<= 1) {
            int t = __shfl_up_sync(0xffffffffu, x, o);
            if (lane >= o) x += t;
        }
        if (lane == 31) warp_sums[wid] = x;
        __syncthreads();
        if (wid == 0) {
            int x2 = warp_sums[lane];
            #pragma unroll
            for (int o = 1; o < 32; o <<= 1) {
                int t = __shfl_up_sync(0xffffffffu, x2, o);
                if (lane >= o) x2 += t;
            }
            warp_sums[lane] = x2;
        }
        __syncthreads();
        int add = (wid > 0) ? warp_sums[wid - 1] : 0;
        int incl = x + add + carry;
        if (i < NNODES) {
            g_off[i] = incl - v;         // exclusive
            g_cnt[i] = 0;                // reset for scatter cursor
        }
        if (tid == 1023) s_incl_last = incl;
        __syncthreads();
        if (tid == 0) s_carry = s_incl_last;
        __syncthreads();
    }
    if (tid == 0) g_off[NNODES] = s_carry;
}

// ---------------- K3: scatter edges into dst-sorted order ----------------
__global__ void k_scatter(const int* __restrict__ ei32) {
    int i = blockIdx.x * blockDim.x + threadIdx.x;
    if (i < NEDGES) {
        int is64 = g_is64;
        int from = is64 ? ei32[2 * i]            : ei32[i];
        int to   = is64 ? ei32[2 * (NEDGES + i)] : ei32[NEDGES + i];
        from = clamp_node(from);
        to   = clamp_node(to);
        int pos = g_off[to] + atomicAdd(&g_cnt[to], 1);
        pos = pos < 0 ? 0 : (pos >= NEDGES ? NEDGES - 1 : pos);
        g_src[pos] = from;
    }
}

// ---------------- K4: GEMM h = x @ W  (M=50000, N=K=128) ----------------
// 256 threads, tile 64 rows x 128 cols, full K.
// x tile in 32 KB static smem; W (64 KB) streamed via L1 (broadcast-coalesced).
__global__ __launch_bounds__(256) void k_gemm(const float* __restrict__ x,
                                              const float* __restrict__ W) {
    __shared__ float sx[64 * FDIM];   // 32 KB

    const int tid = threadIdx.x;
    const int row0 = blockIdx.x * 64;

    float4* sx4 = (float4*)sx;
    const float4* x4 = (const float4*)x;
    #pragma unroll
    for (int i = 0; i < 8; i++) {
        int idx = tid + 256 * i;         // float4 index in tile
        int r = idx >> 5;                // local row
        int grow = row0 + r;
        float4 v = make_float4(0.f, 0.f, 0.f, 0.f);
        if (grow < NNODES) v = x4[grow * 32 + (idx & 31)];
        sx4[idx] = v;
    }
    __syncthreads();

    const int tx = tid & 31;   // cols tx*4 .. tx*4+3
    const int ty = tid >> 5;   // rows ty*8 .. ty*8+7
    const float4* W4 = (const float4*)W;

    float4 acc[8];
    #pragma unroll
    for (int r = 0; r < 8; r++) acc[r] = make_float4(0.f, 0.f, 0.f, 0.f);

    #pragma unroll 4
    for (int k = 0; k < FDIM; k++) {
        float4 b = W4[k * 32 + tx];
        #pragma unroll
        for (int r = 0; r < 8; r++) {
            float a = sx[(ty * 8 + r) * FDIM + k];
            acc[r].x = fmaf(a, b.x, acc[r].x);
            acc[r].y = fmaf(a, b.y, acc[r].y);
            acc[r].z = fmaf(a, b.z, acc[r].z);
            acc[r].w = fmaf(a, b.w, acc[r].w);
        }
    }

    float4* h4 = (float4*)g_h;
    #pragma unroll
    for (int r = 0; r < 8; r++) {
        int grow = row0 + ty * 8 + r;
        if (grow < NNODES) h4[grow * 32 + tx] = acc[r];
    }
}

// ---------------- K5: per-node attention logits ----------------
__global__ __launch_bounds__(256) void k_alpha(const float* __restrict__ att_l,
                                               const float* __restrict__ att_r) {
    int n = blockIdx.x * 8 + (threadIdx.x >> 5);
    int lane = threadIdx.x & 31;
    if (n >= NNODES) return;

    float4 v = ((const float4*)g_h)[n * 32 + lane];
    int head = lane >> 3;
    int dbase = (lane & 7) * 4;
    const float* al = att_l + head * HDIM + dbase;
    const float* ar = att_r + head * HDIM + dbase;

    float pl = v.x * al[0] + v.y * al[1] + v.z * al[2] + v.w * al[3];
    float pr = v.x * ar[0] + v.y * ar[1] + v.z * ar[2] + v.w * ar[3];
    #pragma unroll
    for (int o = 4; o >= 1; o >>= 1) {   // reduce within 8-lane head groups
        pl += __shfl_xor_sync(0xffffffffu, pl, o);
        pr += __shfl_xor_sync(0xffffffffu, pr, o);
    }
    if ((lane & 7) == 0) {
        g_alpha_l[n * NHEADS + head] = pl;
        g_alpha_r[n * NHEADS + head] = pr;
    }
}

// ---------------- K6: per-destination softmax-weighted aggregation ----------------
// one warp per destination; zero float atomics; softmax computed unshifted
// (shift-invariant; |logit| small enough for fp32 exp).
__global__ __launch_bounds__(256) void k_agg(const float* __restrict__ bias,
                                             float* __restrict__ out) {
    int n = blockIdx.x * 8 + (threadIdx.x >> 5);
    int lane = threadIdx.x & 31;
    if (n >= NNODES) return;

    const int head = lane >> 3;
    const float ar = g_alpha_r[n * NHEADS + head];
    const int off0 = g_off[n], off1 = g_off[n + 1];

    float4 acc = make_float4(0.f, 0.f, 0.f, 0.f);
    float den = 0.f;

    const float4* h4 = (const float4*)g_h;

    int e = off0;
    int s_next = (e < off1) ? g_src[e] : 0;
    for (; e < off1; e++) {
        int s = s_next;
        if (e + 1 < off1) s_next = g_src[e + 1];

        float a = g_alpha_l[s * NHEADS + head] + ar;
        a = (a > 0.f) ? a : 0.2f * a;          // leaky_relu(0.2)
        float w = __expf(a);
        float4 v = h4[s * 32 + lane];

        acc.x = fmaf(w, v.x, acc.x);
        acc.y = fmaf(w, v.y, acc.y);
        acc.z = fmaf(w, v.z, acc.z);
        acc.w = fmaf(w, v.w, acc.w);
        den += w;
    }

    float inv = 1.f / (den + 1e-9f);
    float b0 = bias[lane * 4 + 0], b1 = bias[lane * 4 + 1];
    float b2 = bias[lane * 4 + 2], b3 = bias[lane * 4 + 3];
    float4 o;
    o.x = fmaf(acc.x, inv, b0);
    o.y = fmaf(acc.y, inv, b1);
    o.z = fmaf(acc.z, inv, b2);
    o.w = fmaf(acc.w, inv, b3);
    ((float4*)out)[n * 32 + lane] = o;
}

// ---------------- launcher ----------------
extern "C" void kernel_launch(void* const* d_in, const int* in_sizes, int n_in,
                              void* d_out, int out_size) {
    // Identify inputs by element count (robust to ordering):
    //   x: 6,400,000   edge_index: 1,600,000   W: 16,384
    //   att_l / att_r / bias: 128 each (encounter order)
    int ix = -1, ie = -1, iw = -1;
    int small_idx[3] = {-1, -1, -1};
    int ns = 0;
    for (int i = 0; i < n_in; i++) {
        int sz = in_sizes[i];
        if      (sz == NNODES * FDIM) ix = i;
        else if (sz == 2 * NEDGES)    ie = i;
        else if (sz == FDIM * FDIM)   iw = i;
        else if (sz == FDIM && ns < 3) small_idx[ns++] = i;
    }
    if (ix < 0 || ie < 0 || iw < 0 || ns < 3) {   // fallback: positional
        ix = 0; ie = 1; iw = 2;
        small_idx[0] = 3; small_idx[1] = 4; small_idx[2] = 5;
    }

    const float* x     = (const float*)d_in[ix];
    const int*   ei32  = (const int*)d_in[ie];
    const float* W     = (const float*)d_in[iw];
    const float* att_l = (const float*)d_in[small_idx[0]];
    const float* att_r = (const float*)d_in[small_idx[1]];
    const float* bias  = (const float*)d_in[small_idx[2]];
    float*       out   = (float*)d_out;

    k_probe<<<1, 32>>>(ei32);
    k_init_cnt<<<(NNODES + 255) / 256, 256>>>();
    k_hist<<<(NEDGES + 255) / 256, 256>>>(ei32);
    k_scan<<<1, 1024>>>();
    k_scatter<<<(NEDGES + 255) / 256, 256>>>(ei32);
    k_gemm<<<(NNODES + 63) / 64, 256>>>(x, W);
    k_alpha<<<(NNODES + 7) / 8, 256>>>(att_l, att_r);
    k_agg<<<(NNODES + 7) / 8, 256>>>(bias, out);
}

// round 7
// speedup vs baseline: 1.2957x; 1.2957x over previous
#include <cuda_runtime.h>
#include <cstdint>

// Problem constants (match reference: N, E, F_IN, H, D)
#define NNODES 50000
#define NEDGES 800000
#define FDIM   128      // F_IN == H*D == 128
#define NHEADS 4
#define HDIM   32
#define SCAN_NB ((NNODES + 1023) / 1024)   // 49

// ---------------- device scratch (no allocations allowed) ----------------
__device__ __align__(16) float g_h[NNODES * FDIM];     // x @ W (25.6 MB)
__device__ float g_alpha_l[NNODES * NHEADS];
__device__ float g_alpha_r[NNODES * NHEADS];
__device__ int   g_cnt[NNODES];                        // histogram, then cursor
__device__ int   g_off[NNODES + 1];                    // CSR offsets by destination
__device__ int   g_src[NEDGES];                        // src per edge, sorted by dst
__device__ int   g_bsum[SCAN_NB];                      // per-block scan sums
__device__ int   g_boff[SCAN_NB];                      // exclusive block offsets
__device__ int   g_is64;                               // edge dtype flag

__device__ __forceinline__ int clamp_node(int v) {
    v = v < 0 ? 0 : v;
    return v >= NNODES ? NNODES - 1 : v;
}

// ---------------- K-1: probe edge dtype ----------------
// int64-LE data (values < 50000) => all odd int32 words zero.
__global__ void k_probe(const int* __restrict__ ei32) {
    int t = threadIdx.x;                 // 32 threads
    int v = ei32[2 * t + 1];
    unsigned nz = __ballot_sync(0xffffffffu, v != 0);
    if (t == 0) g_is64 = (nz == 0u) ? 1 : 0;
}

// ---------------- K0: zero histogram ----------------
__global__ void k_init_cnt() {
    int i = blockIdx.x * blockDim.x + threadIdx.x;
    if (i < NNODES) g_cnt[i] = 0;
}

// ---------------- K1: histogram of destinations ----------------
__global__ void k_hist(const int* __restrict__ ei32) {
    int i = blockIdx.x * blockDim.x + threadIdx.x;
    if (i < NEDGES) {
        int idx = NEDGES + i;
        int to = g_is64 ? ei32[2 * idx] : ei32[idx];
        atomicAdd(&g_cnt[clamp_node(to)], 1);
    }
}

// ---------------- K2a: block-local exclusive scan (49 blocks x 1024) ----------------
__global__ __launch_bounds__(1024) void k_scan1() {
    __shared__ int wsum[32];
    const int tid = threadIdx.x;
    const int lane = tid & 31, wid = tid >> 5;
    const int i = blockIdx.x * 1024 + tid;

    int v = (i < NNODES) ? g_cnt[i] : 0;
    int x = v;
    #pragma unroll
    for (int o = 1; o < 32; o <<= 1) {
        int t = __shfl_up_sync(0xffffffffu, x, o);
        if (lane >= o) x += t;
    }
    if (lane == 31) wsum[wid] = x;
    __syncthreads();
    if (wid == 0) {
        int x2 = wsum[lane];
        #pragma unroll
        for (int o = 1; o < 32; o <<= 1) {
            int t = __shfl_up_sync(0xffffffffu, x2, o);
            if (lane >= o) x2 += t;
        }
        wsum[lane] = x2;
    }
    __syncthreads();
    int add = (wid > 0) ? wsum[wid - 1] : 0;
    int incl = x + add;
    if (i < NNODES) g_off[i] = incl - v;      // block-local exclusive
    if (tid == 1023) g_bsum[blockIdx.x] = incl;
}

// ---------------- K2b: scan the 49 block sums (1 tiny block) ----------------
__global__ __launch_bounds__(64) void k_scan2() {
    const int tid = threadIdx.x;   // 64 threads, 2 warps
    const int lane = tid & 31, wid = tid >> 5;
    __shared__ int w0_total;

    int v = (tid < SCAN_NB) ? g_bsum[tid] : 0;
    int x = v;
    #pragma unroll
    for (int o = 1; o < 32; o <<= 1) {
        int t = __shfl_up_sync(0xffffffffu, x, o);
        if (lane >= o) x += t;
    }
    if (wid == 0 && lane == 31) w0_total = x;
    __syncthreads();
    int base = (wid == 1) ? w0_total : 0;
    if (tid < SCAN_NB) g_boff[tid] = base + x - v;     // exclusive
    if (tid == SCAN_NB - 1) g_off[NNODES] = base + x;  // grand total (== NEDGES)
}

// ---------------- K2c: add block offsets; zero cnt for scatter cursor ----------------
__global__ __launch_bounds__(1024) void k_scan3() {
    const int i = blockIdx.x * 1024 + threadIdx.x;
    if (i < NNODES) {
        g_off[i] += g_boff[blockIdx.x];
        g_cnt[i] = 0;
    }
}

// ---------------- K3: scatter edges into dst-sorted order ----------------
__global__ void k_scatter(const int* __restrict__ ei32) {
    int i = blockIdx.x * blockDim.x + threadIdx.x;
    if (i < NEDGES) {
        int is64 = g_is64;
        int from = is64 ? ei32[2 * i]            : ei32[i];
        int to   = is64 ? ei32[2 * (NEDGES + i)] : ei32[NEDGES + i];
        from = clamp_node(from);
        to   = clamp_node(to);
        int pos = g_off[to] + atomicAdd(&g_cnt[to], 1);
        pos = pos < 0 ? 0 : (pos >= NEDGES ? NEDGES - 1 : pos);
        g_src[pos] = from;
    }
}

// ---------------- K4: GEMM h = x @ W (+ fused alpha epilogue) ----------------
// 256 threads, tile 64 rows x 128 cols, full K=128.
// x tile in 32 KB static smem; W (64 KB) streamed via L1 (broadcast-coalesced).
// Epilogue: lane tx owns flat channels 4tx..4tx+3 == att layout; intra-8-lane
// shuffle reduction yields alpha_l/alpha_r without re-reading g_h.
__global__ __launch_bounds__(256) void k_gemm(const float* __restrict__ x,
                                              const float* __restrict__ W,
                                              const float* __restrict__ att_l,
                                              const float* __restrict__ att_r) {
    __shared__ float sx[64 * FDIM];   // 32 KB

    const int tid = threadIdx.x;
    const int row0 = blockIdx.x * 64;

    float4* sx4 = (float4*)sx;
    const float4* x4 = (const float4*)x;
    #pragma unroll
    for (int i = 0; i < 8; i++) {
        int idx = tid + 256 * i;         // float4 index in tile
        int r = idx >> 5;                // local row
        int grow = row0 + r;
        float4 v = make_float4(0.f, 0.f, 0.f, 0.f);
        if (grow < NNODES) v = x4[grow * 32 + (idx & 31)];
        sx4[idx] = v;
    }
    __syncthreads();

    const int tx = tid & 31;   // cols tx*4 .. tx*4+3
    const int ty = tid >> 5;   // rows ty*8 .. ty*8+7
    const float4* W4 = (const float4*)W;

    float4 acc[8];
    #pragma unroll
    for (int r = 0; r < 8; r++) acc[r] = make_float4(0.f, 0.f, 0.f, 0.f);

    #pragma unroll 4
    for (int k = 0; k < FDIM; k++) {
        float4 b = W4[k * 32 + tx];
        #pragma unroll
        for (int r = 0; r < 8; r++) {
            float a = sx[(ty * 8 + r) * FDIM + k];
            acc[r].x = fmaf(a, b.x, acc[r].x);
            acc[r].y = fmaf(a, b.y, acc[r].y);
            acc[r].z = fmaf(a, b.z, acc[r].z);
            acc[r].w = fmaf(a, b.w, acc[r].w);
        }
    }

    // store h
    float4* h4 = (float4*)g_h;
    #pragma unroll
    for (int r = 0; r < 8; r++) {
        int grow = row0 + ty * 8 + r;
        if (grow < NNODES) h4[grow * 32 + tx] = acc[r];
    }

    // fused alpha epilogue
    const float4 al4 = ((const float4*)att_l)[tx];
    const float4 ar4 = ((const float4*)att_r)[tx];
    const int head = tx >> 3;
    #pragma unroll
    for (int r = 0; r < 8; r++) {
        float pl = acc[r].x * al4.x + acc[r].y * al4.y + acc[r].z * al4.z + acc[r].w * al4.w;
        float pr = acc[r].x * ar4.x + acc[r].y * ar4.y + acc[r].z * ar4.z + acc[r].w * ar4.w;
        #pragma unroll
        for (int o = 4; o >= 1; o >>= 1) {
            pl += __shfl_xor_sync(0xffffffffu, pl, o);
            pr += __shfl_xor_sync(0xffffffffu, pr, o);
        }
        int grow = row0 + ty * 8 + r;
        if ((tx & 7) == 0 && grow < NNODES) {
            g_alpha_l[grow * NHEADS + head] = pl;
            g_alpha_r[grow * NHEADS + head] = pr;
        }
    }
}

// ---------------- K6: per-destination softmax-weighted aggregation ----------------
// one warp per destination; zero float atomics; softmax computed unshifted
// (shift-invariant; |logit| small enough for fp32 exp).
__global__ __launch_bounds__(256) void k_agg(const float* __restrict__ bias,
                                             float* __restrict__ out) {
    int n = blockIdx.x * 8 + (threadIdx.x >> 5);
    int lane = threadIdx.x & 31;
    if (n >= NNODES) return;

    const int head = lane >> 3;
    const float ar = g_alpha_r[n * NHEADS + head];
    const int off0 = g_off[n], off1 = g_off[n + 1];

    float4 acc = make_float4(0.f, 0.f, 0.f, 0.f);
    float den = 0.f;

    const float4* h4 = (const float4*)g_h;

    int e = off0;
    int s_next = (e < off1) ? g_src[e] : 0;
    for (; e < off1; e++) {
        int s = s_next;
        if (e + 1 < off1) s_next = g_src[e + 1];

        float a = g_alpha_l[s * NHEADS + head] + ar;
        a = (a > 0.f) ? a : 0.2f * a;          // leaky_relu(0.2)
        float w = __expf(a);
        float4 v = h4[s * 32 + lane];

        acc.x = fmaf(w, v.x, acc.x);
        acc.y = fmaf(w, v.y, acc.y);
        acc.z = fmaf(w, v.z, acc.z);
        acc.w = fmaf(w, v.w, acc.w);
        den += w;
    }

    float inv = 1.f / (den + 1e-9f);
    float b0 = bias[lane * 4 + 0], b1 = bias[lane * 4 + 1];
    float b2 = bias[lane * 4 + 2], b3 = bias[lane * 4 + 3];
    float4 o;
    o.x = fmaf(acc.x, inv, b0);
    o.y = fmaf(acc.y, inv, b1);
    o.z = fmaf(acc.z, inv, b2);
    o.w = fmaf(acc.w, inv, b3);
    ((float4*)out)[n * 32 + lane] = o;
}

// ---------------- launcher ----------------
extern "C" void kernel_launch(void* const* d_in, const int* in_sizes, int n_in,
                              void* d_out, int out_size) {
    // Identify inputs by element count (robust to ordering):
    int ix = -1, ie = -1, iw = -1;
    int small_idx[3] = {-1, -1, -1};
    int ns = 0;
    for (int i = 0; i < n_in; i++) {
        int sz = in_sizes[i];
        if      (sz == NNODES * FDIM) ix = i;
        else if (sz == 2 * NEDGES)    ie = i;
        else if (sz == FDIM * FDIM)   iw = i;
        else if (sz == FDIM && ns < 3) small_idx[ns++] = i;
    }
    if (ix < 0 || ie < 0 || iw < 0 || ns < 3) {   // fallback: positional
        ix = 0; ie = 1; iw = 2;
        small_idx[0] = 3; small_idx[1] = 4; small_idx[2] = 5;
    }

    const float* x     = (const float*)d_in[ix];
    const int*   ei32  = (const int*)d_in[ie];
    const float* W     = (const float*)d_in[iw];
    const float* att_l = (const float*)d_in[small_idx[0]];
    const float* att_r = (const float*)d_in[small_idx[1]];
    const float* bias  = (const float*)d_in[small_idx[2]];
    float*       out   = (float*)d_out;

    k_probe<<<1, 32>>>(ei32);
    k_init_cnt<<<(NNODES + 255) / 256, 256>>>();
    k_hist<<<(NEDGES + 255) / 256, 256>>>(ei32);
    k_scan1<<<SCAN_NB, 1024>>>();
    k_scan2<<<1, 64>>>();
    k_scan3<<<SCAN_NB, 1024>>>();
    k_scatter<<<(NEDGES + 255) / 256, 256>>>(ei32);
    k_gemm<<<(NNODES + 63) / 64, 256>>>(x, W, att_l, att_r);
    k_agg<<<(NNODES + 7) / 8, 256>>>(bias, out);
}

// round 8
// speedup vs baseline: 1.7288x; 1.3343x over previous
#include <cuda_runtime.h>
#include <cstdint>

// Problem constants (match reference: N, E, F_IN, H, D)
#define NNODES 50000
#define NEDGES 800000
#define FDIM   128      // F_IN == H*D == 128
#define NHEADS 4
#define HDIM   32
#define SCAN_NB ((NNODES + 1023) / 1024)   // 49

// ---------------- device scratch (no allocations allowed) ----------------
__device__ __align__(16) float g_h[NNODES * FDIM];     // x @ W (25.6 MB)
__device__ float g_alpha_l[NNODES * NHEADS];
__device__ float g_alpha_r[NNODES * NHEADS];
__device__ int   g_cnt[NNODES];                        // histogram, then cursor
__device__ int   g_off[NNODES + 1];                    // CSR offsets by destination
__device__ int   g_src[NEDGES];                        // src per edge, sorted by dst
__device__ int   g_bsum[SCAN_NB];
__device__ int   g_boff[SCAN_NB];
__device__ int   g_is64;                               // edge dtype flag
// W in tf32 mma-fragment layout: [ks(16)][nt(16)][lane(32)] -> (b0,b1)
__device__ __align__(16) uint2 g_wf[16 * 16 * 32];     // 64 KB

__device__ __forceinline__ int clamp_node(int v) {
    v = v < 0 ? 0 : v;
    return v >= NNODES ? NNODES - 1 : v;
}

__device__ __forceinline__ uint32_t f2tf32(float f) {
    uint32_t r;
    asm("cvt.rna.tf32.f32 %0, %1;" : "=r"(r) : "f"(f));
    return r;
}

__device__ __forceinline__ void mma_tf32(float4& d, const uint32_t a0, const uint32_t a1,
                                         const uint32_t a2, const uint32_t a3,
                                         uint32_t b0, uint32_t b1) {
    asm volatile(
        "mma.sync.aligned.m16n8k8.row.col.f32.tf32.tf32.f32 "
        "{%0,%1,%2,%3}, {%4,%5,%6,%7}, {%8,%9}, {%0,%1,%2,%3};"
        : "+f"(d.x), "+f"(d.y), "+f"(d.z), "+f"(d.w)
        : "r"(a0), "r"(a1), "r"(a2), "r"(a3), "r"(b0), "r"(b1));
}

// ---------------- K0: zero histogram + probe edge dtype (fused) ----------------
// int64-LE edge data (values < 50000) => all odd int32 words zero.
__global__ void k_init(const int* __restrict__ ei32) {
    int i = blockIdx.x * blockDim.x + threadIdx.x;
    if (i < NNODES) g_cnt[i] = 0;
    if (blockIdx.x == 0 && threadIdx.x < 32) {
        int v = ei32[2 * threadIdx.x + 1];
        unsigned nz = __ballot_sync(0xffffffffu, v != 0);
        if (threadIdx.x == 0) g_is64 = (nz == 0u) ? 1 : 0;
    }
}

// ---------------- K_wf: reorder W into tf32 fragment layout ----------------
// b0 = W[(ks*8 + lane%4)*128 + nt*8 + lane/4], b1 = same + 4 k-rows.
__global__ void k_wfrag(const float* __restrict__ W) {
    int idx = blockIdx.x * blockDim.x + threadIdx.x;   // 8192 threads
    if (idx >= 16 * 16 * 32) return;
    int lane = idx & 31;
    int tile = idx >> 5;
    int nt = tile & 15;
    int ks = tile >> 4;
    int krow = ks * 8 + (lane & 3);
    int col  = nt * 8 + (lane >> 2);
    uint2 b;
    b.x = f2tf32(W[krow * FDIM + col]);
    b.y = f2tf32(W[(krow + 4) * FDIM + col]);
    g_wf[idx] = b;
}

// ---------------- K1: histogram of destinations ----------------
__global__ void k_hist(const int* __restrict__ ei32) {
    int i = blockIdx.x * blockDim.x + threadIdx.x;
    if (i < NEDGES) {
        int idx = NEDGES + i;
        int to = g_is64 ? ei32[2 * idx] : ei32[idx];
        atomicAdd(&g_cnt[clamp_node(to)], 1);
    }
}

// ---------------- K2a: block-local exclusive scan ----------------
__global__ __launch_bounds__(1024) void k_scan1() {
    __shared__ int wsum[32];
    const int tid = threadIdx.x;
    const int lane = tid & 31, wid = tid >> 5;
    const int i = blockIdx.x * 1024 + tid;

    int v = (i < NNODES) ? g_cnt[i] : 0;
    int x = v;
    #pragma unroll
    for (int o = 1; o < 32; o <<= 1) {
        int t = __shfl_up_sync(0xffffffffu, x, o);
        if (lane >= o) x += t;
    }
    if (lane == 31) wsum[wid] = x;
    __syncthreads();
    if (wid == 0) {
        int x2 = wsum[lane];
        #pragma unroll
        for (int o = 1; o < 32; o <<= 1) {
            int t = __shfl_up_sync(0xffffffffu, x2, o);
            if (lane >= o) x2 += t;
        }
        wsum[lane] = x2;
    }
    __syncthreads();
    int add = (wid > 0) ? wsum[wid - 1] : 0;
    int incl = x + add;
    if (i < NNODES) g_off[i] = incl - v;
    if (tid == 1023) g_bsum[blockIdx.x] = incl;
}

// ---------------- K2b: scan the 49 block sums ----------------
__global__ __launch_bounds__(64) void k_scan2() {
    const int tid = threadIdx.x;
    const int lane = tid & 31, wid = tid >> 5;
    __shared__ int w0_total;

    int v = (tid < SCAN_NB) ? g_bsum[tid] : 0;
    int x = v;
    #pragma unroll
    for (int o = 1; o < 32; o <<= 1) {
        int t = __shfl_up_sync(0xffffffffu, x, o);
        if (lane >= o) x += t;
    }
    if (wid == 0 && lane == 31) w0_total = x;
    __syncthreads();
    int base = (wid == 1) ? w0_total : 0;
    if (tid < SCAN_NB) g_boff[tid] = base + x - v;
    if (tid == SCAN_NB - 1) g_off[NNODES] = base + x;
}

// ---------------- K2c: add block offsets; zero cnt ----------------
__global__ __launch_bounds__(1024) void k_scan3() {
    const int i = blockIdx.x * 1024 + threadIdx.x;
    if (i < NNODES) {
        g_off[i] += g_boff[blockIdx.x];
        g_cnt[i] = 0;
    }
}

// ---------------- K3: scatter edges into dst-sorted order ----------------
__global__ void k_scatter(const int* __restrict__ ei32) {
    int i = blockIdx.x * blockDim.x + threadIdx.x;
    if (i < NEDGES) {
        int is64 = g_is64;
        int from = is64 ? ei32[2 * i]            : ei32[i];
        int to   = is64 ? ei32[2 * (NEDGES + i)] : ei32[NEDGES + i];
        from = clamp_node(from);
        to   = clamp_node(to);
        int pos = g_off[to] + atomicAdd(&g_cnt[to], 1);
        pos = pos < 0 ? 0 : (pos >= NEDGES ? NEDGES - 1 : pos);
        g_src[pos] = from;
    }
}

// ---------------- K4: tensor-core GEMM h = x @ W + fused alpha ----------------
// mma.sync m16n8k8 tf32; x split hi+lo (exact), W pre-rounded to tf32 (g_wf).
// Block = 256 thr (8 warps); warp computes 16 rows x 128 cols. No smem.
__global__ __launch_bounds__(256) void k_gemm(const float* __restrict__ x,
                                              const float* __restrict__ att_l,
                                              const float* __restrict__ att_r) {
    const int wid  = threadIdx.x >> 5;
    const int lane = threadIdx.x & 31;
    const int g = lane >> 2;          // 0..7
    const int c = lane & 3;           // 0..3
    const int row0 = blockIdx.x * 128 + wid * 16;

    const int rA0 = min(row0 + g,     NNODES - 1);
    const int rA1 = min(row0 + g + 8, NNODES - 1);
    const float* xr0 = x + rA0 * FDIM;
    const float* xr1 = x + rA1 * FDIM;

    float4 acc[16];
    #pragma unroll
    for (int nt = 0; nt < 16; nt++) acc[nt] = make_float4(0.f, 0.f, 0.f, 0.f);

    #pragma unroll 4
    for (int ks = 0; ks < 16; ks++) {
        const int k0 = ks * 8;
        // A fragment (rows g,g+8; cols k0+c, k0+c+4), split hi/lo
        float v0 = xr0[k0 + c];
        float v1 = xr1[k0 + c];
        float v2 = xr0[k0 + c + 4];
        float v3 = xr1[k0 + c + 4];
        uint32_t h0 = f2tf32(v0), h1 = f2tf32(v1), h2 = f2tf32(v2), h3 = f2tf32(v3);
        uint32_t l0 = f2tf32(v0 - __uint_as_float(h0));
        uint32_t l1 = f2tf32(v1 - __uint_as_float(h1));
        uint32_t l2 = f2tf32(v2 - __uint_as_float(h2));
        uint32_t l3 = f2tf32(v3 - __uint_as_float(h3));

        const uint2* bf = g_wf + (ks * 16) * 32 + lane;
        #pragma unroll
        for (int nt = 0; nt < 16; nt++) {
            uint2 b = bf[nt * 32];
            mma_tf32(acc[nt], h0, h1, h2, h3, b.x, b.y);
            mma_tf32(acc[nt], l0, l1, l2, l3, b.x, b.y);
        }
    }

    // store h: thread owns (row g: cols 2c,2c+1), (row g+8: same) per n-tile
    const bool ok0 = (row0 + g)     < NNODES;
    const bool ok1 = (row0 + g + 8) < NNODES;
    float* hr0 = g_h + (row0 + g) * FDIM;
    float* hr1 = g_h + (row0 + g + 8) * FDIM;
    #pragma unroll
    for (int nt = 0; nt < 16; nt++) {
        int col = nt * 8 + 2 * c;
        if (ok0) *(float2*)(hr0 + col) = make_float2(acc[nt].x, acc[nt].y);
        if (ok1) *(float2*)(hr1 + col) = make_float2(acc[nt].z, acc[nt].w);
    }

    // fused alpha epilogue: head = nt/4
    #pragma unroll
    for (int hd = 0; hd < NHEADS; hd++) {
        float plg = 0.f, plg8 = 0.f, prg = 0.f, prg8 = 0.f;
        #pragma unroll
        for (int j = 0; j < 4; j++) {
            int nt = hd * 4 + j;
            int col = nt * 8 + 2 * c;
            float2 al2 = *(const float2*)(att_l + col);
            float2 ar2 = *(const float2*)(att_r + col);
            plg  += acc[nt].x * al2.x + acc[nt].y * al2.y;
            plg8 += acc[nt].z * al2.x + acc[nt].w * al2.y;
            prg  += acc[nt].x * ar2.x + acc[nt].y * ar2.y;
            prg8 += acc[nt].z * ar2.x + acc[nt].w * ar2.y;
        }
        #pragma unroll
        for (int o = 1; o <= 2; o <<= 1) {   // reduce over the 4 lanes of a row group
            plg  += __shfl_xor_sync(0xffffffffu, plg,  o);
            plg8 += __shfl_xor_sync(0xffffffffu, plg8, o);
            prg  += __shfl_xor_sync(0xffffffffu, prg,  o);
            prg8 += __shfl_xor_sync(0xffffffffu, prg8, o);
        }
        if (c == 0) {
            if (ok0) {
                g_alpha_l[(row0 + g) * NHEADS + hd] = plg;
                g_alpha_r[(row0 + g) * NHEADS + hd] = prg;
            }
            if (ok1) {
                g_alpha_l[(row0 + g + 8) * NHEADS + hd] = plg8;
                g_alpha_r[(row0 + g + 8) * NHEADS + hd] = prg8;
            }
        }
    }
}

// ---------------- K6: per-destination softmax-weighted aggregation ----------------
// one warp per destination; zero float atomics; unrolled x2 for MLP.
__global__ __launch_bounds__(256) void k_agg(const float* __restrict__ bias,
                                             float* __restrict__ out) {
    int n = blockIdx.x * 8 + (threadIdx.x >> 5);
    int lane = threadIdx.x & 31;
    if (n >= NNODES) return;

    const int head = lane >> 3;
    const float ar = g_alpha_r[n * NHEADS + head];
    const int off0 = g_off[n], off1 = g_off[n + 1];

    float4 acc = make_float4(0.f, 0.f, 0.f, 0.f);
    float den = 0.f;
    const float4* h4 = (const float4*)g_h;

    int e = off0;
    for (; e + 1 < off1; e += 2) {
        int s0 = g_src[e];
        int s1 = g_src[e + 1];
        float a0 = g_alpha_l[s0 * NHEADS + head] + ar;
        float a1 = g_alpha_l[s1 * NHEADS + head] + ar;
        float4 v0 = h4[s0 * 32 + lane];
        float4 v1 = h4[s1 * 32 + lane];
        a0 = (a0 > 0.f) ? a0 : 0.2f * a0;
        a1 = (a1 > 0.f) ? a1 : 0.2f * a1;
        float w0 = __expf(a0);
        float w1 = __expf(a1);
        acc.x = fmaf(w0, v0.x, fmaf(w1, v1.x, acc.x));
        acc.y = fmaf(w0, v0.y, fmaf(w1, v1.y, acc.y));
        acc.z = fmaf(w0, v0.z, fmaf(w1, v1.z, acc.z));
        acc.w = fmaf(w0, v0.w, fmaf(w1, v1.w, acc.w));
        den += w0 + w1;
    }
    if (e < off1) {
        int s = g_src[e];
        float a = g_alpha_l[s * NHEADS + head] + ar;
        a = (a > 0.f) ? a : 0.2f * a;
        float w = __expf(a);
        float4 v = h4[s * 32 + lane];
        acc.x = fmaf(w, v.x, acc.x);
        acc.y = fmaf(w, v.y, acc.y);
        acc.z = fmaf(w, v.z, acc.z);
        acc.w = fmaf(w, v.w, acc.w);
        den += w;
    }

    float inv = 1.f / (den + 1e-9f);
    float b0 = bias[lane * 4 + 0], b1 = bias[lane * 4 + 1];
    float b2 = bias[lane * 4 + 2], b3 = bias[lane * 4 + 3];
    float4 o;
    o.x = fmaf(acc.x, inv, b0);
    o.y = fmaf(acc.y, inv, b1);
    o.z = fmaf(acc.z, inv, b2);
    o.w = fmaf(acc.w, inv, b3);
    ((float4*)out)[n * 32 + lane] = o;
}

// ---------------- launcher ----------------
extern "C" void kernel_launch(void* const* d_in, const int* in_sizes, int n_in,
                              void* d_out, int out_size) {
    int ix = -1, ie = -1, iw = -1;
    int small_idx[3] = {-1, -1, -1};
    int ns = 0;
    for (int i = 0; i < n_in; i++) {
        int sz = in_sizes[i];
        if      (sz == NNODES * FDIM) ix = i;
        else if (sz == 2 * NEDGES)    ie = i;
        else if (sz == FDIM * FDIM)   iw = i;
        else if (sz == FDIM && ns < 3) small_idx[ns++] = i;
    }
    if (ix < 0 || ie < 0 || iw < 0 || ns < 3) {
        ix = 0; ie = 1; iw = 2;
        small_idx[0] = 3; small_idx[1] = 4; small_idx[2] = 5;
    }

    const float* x     = (const float*)d_in[ix];
    const int*   ei32  = (const int*)d_in[ie];
    const float* W     = (const float*)d_in[iw];
    const float* att_l = (const float*)d_in[small_idx[0]];
    const float* att_r = (const float*)d_in[small_idx[1]];
    const float* bias  = (const float*)d_in[small_idx[2]];
    float*       out   = (float*)d_out;

    k_init<<<(NNODES + 255) / 256, 256>>>(ei32);
    k_wfrag<<<32, 256>>>(W);
    k_hist<<<(NEDGES + 255) / 256, 256>>>(ei32);
    k_scan1<<<SCAN_NB, 1024>>>();
    k_scan2<<<1, 64>>>();
    k_scan3<<<SCAN_NB, 1024>>>();
    k_scatter<<<(NEDGES + 255) / 256, 256>>>(ei32);
    k_gemm<<<(NNODES + 127) / 128, 256>>>(x, att_l, att_r);
    k_agg<<<(NNODES + 7) / 8, 256>>>(bias, out);
}

// round 9
// speedup vs baseline: 1.7940x; 1.0377x over previous
#include <cuda_runtime.h>
#include <cuda_fp16.h>
#include <cstdint>

// Problem constants (match reference: N, E, F_IN, H, D)
#define NNODES 50000
#define NEDGES 800000
#define FDIM   128      // F_IN == H*D == 128
#define NHEADS 4
#define HDIM   32
#define SCAN_NB ((NNODES + 1023) / 1024)   // 49

// ---------------- device scratch (no allocations allowed) ----------------
__device__ __align__(16) __half g_hh[NNODES * FDIM];   // x @ W in fp16 (12.8 MB)
__device__ float g_alpha_l[NNODES * NHEADS];
__device__ float g_alpha_r[NNODES * NHEADS];
__device__ int   g_cnt[NNODES];                        // histogram, then cursor
__device__ int   g_off[NNODES + 1];                    // CSR offsets by destination
__device__ int   g_src[NEDGES];                        // src per edge, sorted by dst
__device__ int   g_bsum[SCAN_NB];
__device__ int   g_boff[SCAN_NB];
__device__ int   g_is64;                               // edge dtype flag
// W in tf32 mma-fragment layout: [ks(16)][nt(16)][lane(32)] -> (b0,b1)
__device__ __align__(16) uint2 g_wf[16 * 16 * 32];     // 64 KB

__device__ __forceinline__ int clamp_node(int v) {
    v = v < 0 ? 0 : v;
    return v >= NNODES ? NNODES - 1 : v;
}

__device__ __forceinline__ uint32_t f2tf32(float f) {
    uint32_t r;
    asm("cvt.rna.tf32.f32 %0, %1;" : "=r"(r) : "f"(f));
    return r;
}

__device__ __forceinline__ void mma_tf32(float4& d, const uint32_t a0, const uint32_t a1,
                                         const uint32_t a2, const uint32_t a3,
                                         uint32_t b0, uint32_t b1) {
    asm volatile(
        "mma.sync.aligned.m16n8k8.row.col.f32.tf32.tf32.f32 "
        "{%0,%1,%2,%3}, {%4,%5,%6,%7}, {%8,%9}, {%0,%1,%2,%3};"
        : "+f"(d.x), "+f"(d.y), "+f"(d.z), "+f"(d.w)
        : "r"(a0), "r"(a1), "r"(a2), "r"(a3), "r"(b0), "r"(b1));
}

// ---------------- K0 (fused): zero histogram + W->tf32 fragments + dtype probe ----
__global__ void k_init(const int* __restrict__ ei32, const float* __restrict__ W) {
    int t = blockIdx.x * blockDim.x + threadIdx.x;
    if (t < NNODES) g_cnt[t] = 0;
    if (t < 16 * 16 * 32) {
        int lane = t & 31;
        int tile = t >> 5;
        int nt = tile & 15;
        int ks = tile >> 4;
        int krow = ks * 8 + (lane & 3);
        int col  = nt * 8 + (lane >> 2);
        uint2 b;
        b.x = f2tf32(W[krow * FDIM + col]);
        b.y = f2tf32(W[(krow + 4) * FDIM + col]);
        g_wf[t] = b;
    }
    if (blockIdx.x == 0 && threadIdx.x < 32) {
        // int64-LE edge data (values < 50000) => all odd int32 words zero
        int v = ei32[2 * threadIdx.x + 1];
        unsigned nz = __ballot_sync(0xffffffffu, v != 0);
        if (threadIdx.x == 0) g_is64 = (nz == 0u) ? 1 : 0;
    }
}

// ---------------- K1: histogram of destinations ----------------
__global__ void k_hist(const int* __restrict__ ei32) {
    int i = blockIdx.x * blockDim.x + threadIdx.x;
    if (i < NEDGES) {
        int idx = NEDGES + i;
        int to = g_is64 ? ei32[2 * idx] : ei32[idx];
        atomicAdd(&g_cnt[clamp_node(to)], 1);
    }
}

// ---------------- K2a: block-local exclusive scan ----------------
__global__ __launch_bounds__(1024) void k_scan1() {
    __shared__ int wsum[32];
    const int tid = threadIdx.x;
    const int lane = tid & 31, wid = tid >> 5;
    const int i = blockIdx.x * 1024 + tid;

    int v = (i < NNODES) ? g_cnt[i] : 0;
    int x = v;
    #pragma unroll
    for (int o = 1; o < 32; o <<= 1) {
        int t = __shfl_up_sync(0xffffffffu, x, o);
        if (lane >= o) x += t;
    }
    if (lane == 31) wsum[wid] = x;
    __syncthreads();
    if (wid == 0) {
        int x2 = wsum[lane];
        #pragma unroll
        for (int o = 1; o < 32; o <<= 1) {
            int t = __shfl_up_sync(0xffffffffu, x2, o);
            if (lane >= o) x2 += t;
        }
        wsum[lane] = x2;
    }
    __syncthreads();
    int add = (wid > 0) ? wsum[wid - 1] : 0;
    int incl = x + add;
    if (i < NNODES) g_off[i] = incl - v;
    if (tid == 1023) g_bsum[blockIdx.x] = incl;
}

// ---------------- K2b: scan the 49 block sums ----------------
__global__ __launch_bounds__(64) void k_scan2() {
    const int tid = threadIdx.x;
    const int lane = tid & 31, wid = tid >> 5;
    __shared__ int w0_total;

    int v = (tid < SCAN_NB) ? g_bsum[tid] : 0;
    int x = v;
    #pragma unroll
    for (int o = 1; o < 32; o <<= 1) {
        int t = __shfl_up_sync(0xffffffffu, x, o);
        if (lane >= o) x += t;
    }
    if (wid == 0 && lane == 31) w0_total = x;
    __syncthreads();
    int base = (wid == 1) ? w0_total : 0;
    if (tid < SCAN_NB) g_boff[tid] = base + x - v;
    if (tid == SCAN_NB - 1) g_off[NNODES] = base + x;
}

// ---------------- K2c: add block offsets; zero cnt ----------------
__global__ __launch_bounds__(1024) void k_scan3() {
    const int i = blockIdx.x * 1024 + threadIdx.x;
    if (i < NNODES) {
        g_off[i] += g_boff[blockIdx.x];
        g_cnt[i] = 0;
    }
}

// ---------------- K3: scatter edges into dst-sorted order ----------------
__global__ void k_scatter(const int* __restrict__ ei32) {
    int i = blockIdx.x * blockDim.x + threadIdx.x;
    if (i < NEDGES) {
        int is64 = g_is64;
        int from = is64 ? ei32[2 * i]            : ei32[i];
        int to   = is64 ? ei32[2 * (NEDGES + i)] : ei32[NEDGES + i];
        from = clamp_node(from);
        to   = clamp_node(to);
        int pos = g_off[to] + atomicAdd(&g_cnt[to], 1);
        pos = pos < 0 ? 0 : (pos >= NEDGES ? NEDGES - 1 : pos);
        g_src[pos] = from;
    }
}

// ---------------- K4: tensor-core GEMM h = x @ W + fused alpha ----------------
// mma.sync m16n8k8 tf32; x split hi+lo (exact), W pre-rounded to tf32 (g_wf).
// h stored as fp16 (halves aggregation gather traffic); alpha from fp32 accs.
__global__ __launch_bounds__(256) void k_gemm(const float* __restrict__ x,
                                              const float* __restrict__ att_l,
                                              const float* __restrict__ att_r) {
    const int wid  = threadIdx.x >> 5;
    const int lane = threadIdx.x & 31;
    const int g = lane >> 2;          // 0..7
    const int c = lane & 3;           // 0..3
    const int row0 = blockIdx.x * 128 + wid * 16;

    const int rA0 = min(row0 + g,     NNODES - 1);
    const int rA1 = min(row0 + g + 8, NNODES - 1);
    const float* xr0 = x + rA0 * FDIM;
    const float* xr1 = x + rA1 * FDIM;

    float4 acc[16];
    #pragma unroll
    for (int nt = 0; nt < 16; nt++) acc[nt] = make_float4(0.f, 0.f, 0.f, 0.f);

    #pragma unroll 4
    for (int ks = 0; ks < 16; ks++) {
        const int k0 = ks * 8;
        float v0 = xr0[k0 + c];
        float v1 = xr1[k0 + c];
        float v2 = xr0[k0 + c + 4];
        float v3 = xr1[k0 + c + 4];
        uint32_t h0 = f2tf32(v0), h1 = f2tf32(v1), h2 = f2tf32(v2), h3 = f2tf32(v3);
        uint32_t l0 = f2tf32(v0 - __uint_as_float(h0));
        uint32_t l1 = f2tf32(v1 - __uint_as_float(h1));
        uint32_t l2 = f2tf32(v2 - __uint_as_float(h2));
        uint32_t l3 = f2tf32(v3 - __uint_as_float(h3));

        const uint2* bf = g_wf + (ks * 16) * 32 + lane;
        #pragma unroll
        for (int nt = 0; nt < 16; nt++) {
            uint2 b = bf[nt * 32];
            mma_tf32(acc[nt], h0, h1, h2, h3, b.x, b.y);
            mma_tf32(acc[nt], l0, l1, l2, l3, b.x, b.y);
        }
    }

    // store h (fp16): thread owns cols nt*8+2c..+1 for rows g and g+8
    const bool ok0 = (row0 + g)     < NNODES;
    const bool ok1 = (row0 + g + 8) < NNODES;
    __half* hr0 = g_hh + (row0 + g) * FDIM;
    __half* hr1 = g_hh + (row0 + g + 8) * FDIM;
    #pragma unroll
    for (int nt = 0; nt < 16; nt++) {
        int col = nt * 8 + 2 * c;
        if (ok0) *(__half2*)(hr0 + col) = __floats2half2_rn(acc[nt].x, acc[nt].y);
        if (ok1) *(__half2*)(hr1 + col) = __floats2half2_rn(acc[nt].z, acc[nt].w);
    }

    // fused alpha epilogue (exact fp32 accs): head = nt/4
    #pragma unroll
    for (int hd = 0; hd < NHEADS; hd++) {
        float plg = 0.f, plg8 = 0.f, prg = 0.f, prg8 = 0.f;
        #pragma unroll
        for (int j = 0; j < 4; j++) {
            int nt = hd * 4 + j;
            int col = nt * 8 + 2 * c;
            float2 al2 = *(const float2*)(att_l + col);
            float2 ar2 = *(const float2*)(att_r + col);
            plg  += acc[nt].x * al2.x + acc[nt].y * al2.y;
            plg8 += acc[nt].z * al2.x + acc[nt].w * al2.y;
            prg  += acc[nt].x * ar2.x + acc[nt].y * ar2.y;
            prg8 += acc[nt].z * ar2.x + acc[nt].w * ar2.y;
        }
        #pragma unroll
        for (int o = 1; o <= 2; o <<= 1) {
            plg  += __shfl_xor_sync(0xffffffffu, plg,  o);
            plg8 += __shfl_xor_sync(0xffffffffu, plg8, o);
            prg  += __shfl_xor_sync(0xffffffffu, prg,  o);
            prg8 += __shfl_xor_sync(0xffffffffu, prg8, o);
        }
        if (c == 0) {
            if (ok0) {
                g_alpha_l[(row0 + g) * NHEADS + hd] = plg;
                g_alpha_r[(row0 + g) * NHEADS + hd] = prg;
            }
            if (ok1) {
                g_alpha_l[(row0 + g + 8) * NHEADS + hd] = plg8;
                g_alpha_r[(row0 + g + 8) * NHEADS + hd] = prg8;
            }
        }
    }
}

// ---------------- K6: per-destination softmax-weighted aggregation ----------------
// one warp per destination; fp16 h gather (256B/edge); zero float atomics.
__global__ __launch_bounds__(256) void k_agg(const float* __restrict__ bias,
                                             float* __restrict__ out) {
    int n = blockIdx.x * 8 + (threadIdx.x >> 5);
    int lane = threadIdx.x & 31;
    if (n >= NNODES) return;

    const int head = lane >> 3;
    const float ar = g_alpha_r[n * NHEADS + head];
    const int off0 = g_off[n], off1 = g_off[n + 1];

    float4 acc = make_float4(0.f, 0.f, 0.f, 0.f);
    float den = 0.f;
    const uint2* h2 = (const uint2*)g_hh;   // lane reads 4 halves (8B)

    int e = off0;
    for (; e + 1 < off1; e += 2) {
        int s0 = g_src[e];
        int s1 = g_src[e + 1];
        float a0 = g_alpha_l[s0 * NHEADS + head] + ar;
        float a1 = g_alpha_l[s1 * NHEADS + head] + ar;
        uint2 u0 = h2[s0 * 32 + lane];
        uint2 u1 = h2[s1 * 32 + lane];
        a0 = (a0 > 0.f) ? a0 : 0.2f * a0;
        a1 = (a1 > 0.f) ? a1 : 0.2f * a1;
        float w0 = __expf(a0);
        float w1 = __expf(a1);
        float2 p00 = __half22float2(*(const __half2*)&u0.x);
        float2 p01 = __half22float2(*(const __half2*)&u0.y);
        float2 p10 = __half22float2(*(const __half2*)&u1.x);
        float2 p11 = __half22float2(*(const __half2*)&u1.y);
        acc.x = fmaf(w0, p00.x, fmaf(w1, p10.x, acc.x));
        acc.y = fmaf(w0, p00.y, fmaf(w1, p10.y, acc.y));
        acc.z = fmaf(w0, p01.x, fmaf(w1, p11.x, acc.z));
        acc.w = fmaf(w0, p01.y, fmaf(w1, p11.y, acc.w));
        den += w0 + w1;
    }
    if (e < off1) {
        int s = g_src[e];
        float a = g_alpha_l[s * NHEADS + head] + ar;
        a = (a > 0.f) ? a : 0.2f * a;
        float w = __expf(a);
        uint2 u = h2[s * 32 + lane];
        float2 p0 = __half22float2(*(const __half2*)&u.x);
        float2 p1 = __half22float2(*(const __half2*)&u.y);
        acc.x = fmaf(w, p0.x, acc.x);
        acc.y = fmaf(w, p0.y, acc.y);
        acc.z = fmaf(w, p1.x, acc.z);
        acc.w = fmaf(w, p1.y, acc.w);
        den += w;
    }

    float inv = 1.f / (den + 1e-9f);
    float b0 = bias[lane * 4 + 0], b1 = bias[lane * 4 + 1];
    float b2 = bias[lane * 4 + 2], b3 = bias[lane * 4 + 3];
    float4 o;
    o.x = fmaf(acc.x, inv, b0);
    o.y = fmaf(acc.y, inv, b1);
    o.z = fmaf(acc.z, inv, b2);
    o.w = fmaf(acc.w, inv, b3);
    ((float4*)out)[n * 32 + lane] = o;
}

// ---------------- launcher ----------------
extern "C" void kernel_launch(void* const* d_in, const int* in_sizes, int n_in,
                              void* d_out, int out_size) {
    int ix = -1, ie = -1, iw = -1;
    int small_idx[3] = {-1, -1, -1};
    int ns = 0;
    for (int i = 0; i < n_in; i++) {
        int sz = in_sizes[i];
        if      (sz == NNODES * FDIM) ix = i;
        else if (sz == 2 * NEDGES)    ie = i;
        else if (sz == FDIM * FDIM)   iw = i;
        else if (sz == FDIM && ns < 3) small_idx[ns++] = i;
    }
    if (ix < 0 || ie < 0 || iw < 0 || ns < 3) {
        ix = 0; ie = 1; iw = 2;
        small_idx[0] = 3; small_idx[1] = 4; small_idx[2] = 5;
    }

    const float* x     = (const float*)d_in[ix];
    const int*   ei32  = (const int*)d_in[ie];
    const float* W     = (const float*)d_in[iw];
    const float* att_l = (const float*)d_in[small_idx[0]];
    const float* att_r = (const float*)d_in[small_idx[1]];
    const float* bias  = (const float*)d_in[small_idx[2]];
    float*       out   = (float*)d_out;

    k_init<<<(NNODES + 255) / 256, 256>>>(ei32, W);
    k_hist<<<(NEDGES + 255) / 256, 256>>>(ei32);
    k_scan1<<<SCAN_NB, 1024>>>();
    k_scan2<<<1, 64>>>();
    k_scan3<<<SCAN_NB, 1024>>>();
    k_scatter<<<(NEDGES + 255) / 256, 256>>>(ei32);
    k_gemm<<<(NNODES + 127) / 128, 256>>>(x, att_l, att_r);
    k_agg<<<(NNODES + 7) / 8, 256>>>(bias, out);
}